// round 13
// baseline (speedup 1.0000x reference)
#include <cuda_runtime.h>
#include <cuda_bf16.h>
#include <math.h>
#include <stdint.h>

#define NN 8192
#define DD 256

// ---------------- device scratch (every array overwritten or reset each replay) ----------------
__device__ __align__(16) __nv_bfloat16 g_Ab[NN * DD];   // x1 bf16
__device__ __align__(16) __nv_bfloat16 g_Bb[NN * DD];   // x2 bf16
__device__ float g_Cf[DD * DD];    // x2^T x2 (fp32 accum; zeroed by prep each replay)
__device__ float g_Bf[DD * DD];    // x1^T x1
__device__ __align__(16) __nv_bfloat16 g_Cfb[DD * DD];  // bf16 copies for quad
__device__ __align__(16) __nv_bfloat16 g_Bfb[DD * DD];
__device__ float g_v1p[256 * 256], g_v2p[256 * 256];    // per-block column-sum partials
__device__ float g_v1[DD], g_v2[DD];                    // written by cvt (plain store)
__device__ float g_d[NN];                               // exact fp32 diagonal, written by prep
__device__ float g_S1r[NN], g_S1c[NN];                  // written by quad
__device__ float g_S2r[NN], g_S2c[NN];                  // written by quad
__device__ float g_lsum;                                // reset by cvt each replay
__device__ unsigned g_tkf;                              // reset by cvt each replay

// ---------------- prep: f32->bf16, v-partials, exact diagonal, zero Gram (R10 exact) ----------------
__global__ void prep_kernel(const float* __restrict__ x1, const float* __restrict__ x2) {
    __shared__ float sd[32][257];
    const int t = threadIdx.x;            // column 0..255
    const int b = blockIdx.x;
    const int r0 = b * 32;
    float v1 = 0.f, v2 = 0.f;
#pragma unroll 4
    for (int r = 0; r < 32; r++) {
        int idx = (r0 + r) * DD + t;
        float f1 = x1[idx], f2 = x2[idx];
        g_Ab[idx] = __float2bfloat16(f1);
        g_Bb[idx] = __float2bfloat16(f2);
        v1 += f1;
        v2 += f2;
        sd[r][t] = f1 * f2;
    }
    g_v1p[b * 256 + t] = v1;              // plain store, no pre-zero needed
    g_v2p[b * 256 + t] = v2;
    int i = b * 256 + t;                  // covers 65536 = DD*DD
    g_Cf[i] = 0.f;
    g_Bf[i] = 0.f;
    __syncthreads();
    const int warp = t >> 5, lane = t & 31;
#pragma unroll
    for (int rr = 0; rr < 4; rr++) {      // warp w reduces rows 4w..4w+3
        int row = warp * 4 + rr;
        float s = 0.f;
#pragma unroll
        for (int k = lane; k < 256; k += 32) s += sd[row][k];
#pragma unroll
        for (int o = 16; o; o >>= 1) s += __shfl_xor_sync(~0u, s, o);
        if (lane == 0) g_d[r0 + row] = s;
    }
}

// ---------------- PTX helpers ----------------
__device__ __forceinline__ void cp_async16(uint32_t dst, const void* src) {
    asm volatile("cp.async.cg.shared.global [%0], [%1], 16;" :: "r"(dst), "l"(src));
}
__device__ __forceinline__ void ldsm_x4(uint32_t& r0, uint32_t& r1, uint32_t& r2, uint32_t& r3,
                                        uint32_t addr) {
    asm volatile("ldmatrix.sync.aligned.m8n8.x4.shared.b16 {%0,%1,%2,%3}, [%4];"
                 : "=r"(r0), "=r"(r1), "=r"(r2), "=r"(r3) : "r"(addr));
}
__device__ __forceinline__ void ldsm_x4_t(uint32_t& r0, uint32_t& r1, uint32_t& r2, uint32_t& r3,
                                          uint32_t addr) {
    asm volatile("ldmatrix.sync.aligned.m8n8.x4.trans.shared.b16 {%0,%1,%2,%3}, [%4];"
                 : "=r"(r0), "=r"(r1), "=r"(r2), "=r"(r3) : "r"(addr));
}
__device__ __forceinline__ void mma_bf16(float c[4], uint32_t a0, uint32_t a1, uint32_t a2,
                                         uint32_t a3, uint32_t b0, uint32_t b1) {
    asm volatile("mma.sync.aligned.m16n8k16.row.col.f32.bf16.bf16.f32 "
                 "{%0,%1,%2,%3}, {%4,%5,%6,%7}, {%8,%9}, {%0,%1,%2,%3};"
                 : "+f"(c[0]), "+f"(c[1]), "+f"(c[2]), "+f"(c[3])
                 : "r"(a0), "r"(a1), "r"(a2), "r"(a3), "r"(b0), "r"(b1));
}

// ---------------- syrk: C = X^T X via split-K, ldmatrix.trans (R10 exact, PASSING) ----------------
#define SK_LD 264
#define SK_STAGE (32 * SK_LD)       // elems per stage

__global__ void __launch_bounds__(256, 2) syrk_kernel() {
    __shared__ __nv_bfloat16 sm[2 * SK_STAGE];
    uint32_t sb = (uint32_t)__cvta_generic_to_shared(sm);
    const int tid = threadIdx.x, lane = tid & 31, warp = tid >> 5;
    const int wm = warp >> 2, wn = warp & 3;
    const int ta = blockIdx.y >> 1, tb = blockIdx.y & 1;
    const __nv_bfloat16* X = blockIdx.z ? g_Ab : g_Bb;
    float* OUT = blockIdx.z ? g_Bf : g_Cf;
    const int r0 = blockIdx.x * 256;

    float acc[4][4][4];
#pragma unroll
    for (int mi = 0; mi < 4; mi++)
#pragma unroll
        for (int ni = 0; ni < 4; ni++)
#pragma unroll
            for (int q = 0; q < 4; q++) acc[mi][ni][q] = 0.f;

    auto load_stage = [&](int kt, int buf) {
#pragma unroll
        for (int i = 0; i < 4; i++) {
            int c = tid + i * 256;
            int row = c >> 5, col8 = c & 31;
            int gcol = (col8 < 16) ? ta * 128 + col8 * 8 : tb * 128 + (col8 - 16) * 8;
            cp_async16(sb + (uint32_t)(buf * SK_STAGE + row * SK_LD + col8 * 8) * 2u,
                       X + (size_t)(r0 + kt * 32 + row) * DD + gcol);
        }
    };

    load_stage(0, 0);
    asm volatile("cp.async.commit_group;" ::: "memory");
    for (int kt = 0; kt < 8; kt++) {
        const int buf = kt & 1;
        if (kt < 7) {
            load_stage(kt + 1, buf ^ 1);
            asm volatile("cp.async.commit_group;" ::: "memory");
            asm volatile("cp.async.wait_group 1;" ::: "memory");
        } else {
            asm volatile("cp.async.wait_group 0;" ::: "memory");
        }
        __syncthreads();
        uint32_t base = sb + (uint32_t)(buf * SK_STAGE) * 2u;
#pragma unroll
        for (int kk = 0; kk < 32; kk += 16) {
            uint32_t a[4][4], b[4][2];
            int krA = kk + (lane & 7) + ((lane >> 4) & 1) * 8;
            int mofA = ((lane >> 3) & 1) * 8;
#pragma unroll
            for (int mi = 0; mi < 4; mi++) {
                int m = wm * 64 + mi * 16 + mofA;
                ldsm_x4_t(a[mi][0], a[mi][1], a[mi][2], a[mi][3],
                          base + (uint32_t)(krA * SK_LD + m) * 2u);
            }
            int krB = kk + (lane & 7) + ((lane >> 3) & 1) * 8;
            int nofB = ((lane >> 4) & 1) * 8;
#pragma unroll
            for (int j = 0; j < 2; j++) {
                int n = 128 + wn * 32 + j * 16 + nofB;
                ldsm_x4_t(b[2 * j][0], b[2 * j][1], b[2 * j + 1][0], b[2 * j + 1][1],
                          base + (uint32_t)(krB * SK_LD + n) * 2u);
            }
#pragma unroll
            for (int mi = 0; mi < 4; mi++)
#pragma unroll
                for (int ni = 0; ni < 4; ni++)
                    mma_bf16(acc[mi][ni], a[mi][0], a[mi][1], a[mi][2], a[mi][3],
                             b[ni][0], b[ni][1]);
        }
        __syncthreads();
    }

#pragma unroll
    for (int mi = 0; mi < 4; mi++)
#pragma unroll
        for (int ni = 0; ni < 4; ni++)
#pragma unroll
            for (int h = 0; h < 2; h++)
#pragma unroll
                for (int w = 0; w < 2; w++) {
                    int gm = ta * 128 + wm * 64 + mi * 16 + (lane >> 2) + 8 * h;
                    int gn = tb * 128 + wn * 32 + ni * 8 + 2 * (lane & 3) + w;
                    atomicAdd(&OUT[gm * DD + gn], acc[mi][ni][2 * h + w]);
                }
}

// ---------------- cvt: Gram fp32->bf16, v-partial reduction, counter reset (R10 exact) ----------------
__global__ void cvt_kernel() {
    const int bid = blockIdx.x, t = threadIdx.x;
    if (bid < 128) {
        int i = (bid * 256 + t) * 2;
        float2 c = *(const float2*)(g_Cf + i);
        float2 b = *(const float2*)(g_Bf + i);
        *(__nv_bfloat162*)(g_Cfb + i) = __floats2bfloat162_rn(c.x, c.y);
        *(__nv_bfloat162*)(g_Bfb + i) = __floats2bfloat162_rn(b.x, b.y);
    } else {
        const float* P = (bid == 128) ? g_v1p : g_v2p;
        float s = 0.f;
        for (int b = 0; b < 256; b++) s += P[b * 256 + t];
        if (bid == 128) g_v1[t] = s;
        else            g_v2[t] = s;
        if (bid == 129 && t == 0) { g_lsum = 0.f; g_tkf = 0u; }   // before finalize, each replay
    }
}

// ---------------- quad: chunked-B (4 x 64 rows), 3 CTAs/SM — B load FIXED (8 iters = 2048 chunks) ----------------
// grid: x = 128 row-blocks of 64 rows, y = 2 matrices
#define QA_LD 264
#define SMA_ELEMS (64 * QA_LD)
#define SMB_ELEMS (64 * QA_LD)
#define SMEM_Q ((SMA_ELEMS + SMB_ELEMS) * 2 + (64 + 256 + 256) * 4)

__global__ void __launch_bounds__(256, 3) quad_kernel() {
    extern __shared__ char qs[];
    __nv_bfloat16* smA = (__nv_bfloat16*)qs;
    __nv_bfloat16* smB = smA + SMA_ELEMS;
    float* sRow = (float*)(qs + (SMA_ELEMS + SMB_ELEMS) * 2);
    float* sS1  = sRow + 64;
    float* sV   = sS1 + 256;
    uint32_t sa = (uint32_t)__cvta_generic_to_shared(smA);
    uint32_t sbB = (uint32_t)__cvta_generic_to_shared(smB);
    const int tid = threadIdx.x, lane = tid & 31, warp = tid >> 5;
    const int wm = warp >> 2, wn = warp & 3;   // wm 0..1 (32 rows), wn 0..3 (16 cols)
    const int rb = blockIdx.x;
    const __nv_bfloat16* A = blockIdx.y ? g_Bb : g_Ab;
    const __nv_bfloat16* Cb = blockIdx.y ? g_Bfb : g_Cfb;
    const float* Vsrc = blockIdx.y ? g_v1 : g_v2;
    float* OUT  = blockIdx.y ? g_S2c : g_S2r;
    float* OUT1 = blockIdx.y ? g_S1c : g_S1r;

    // A tile 64x256 resident (2048 chunks of 16B)
#pragma unroll
    for (int i = 0; i < 8; i++) {
        int c = tid + i * 256;
        int row = c >> 5, col8 = c & 31;
        cp_async16(sa + (uint32_t)(row * QA_LD + col8 * 8) * 2u,
                   A + (size_t)(rb * 64 + row) * DD + col8 * 8);
    }
    asm volatile("cp.async.commit_group;" ::: "memory");
    if (tid < 64) sRow[tid] = 0.f;
    sV[tid] = Vsrc[tid];

    float s2[2][2];
    s2[0][0] = s2[0][1] = s2[1][0] = s2[1][1] = 0.f;

    for (int nb = 0; nb < 4; nb++) {
        if (nb) __syncthreads();   // smB safe to overwrite
        // B chunk: C rows nb*64 .. +64 = 64 rows x 32 col8 = 2048 chunks of 16B (FIXED: 8 iters)
#pragma unroll
        for (int i = 0; i < 8; i++) {
            int c = tid + i * 256;
            int row = c >> 5, col8 = c & 31;
            cp_async16(sbB + (uint32_t)(row * QA_LD + col8 * 8) * 2u,
                       Cb + (size_t)(nb * 64 + row) * DD + col8 * 8);
        }
        asm volatile("cp.async.commit_group;" ::: "memory");
        asm volatile("cp.async.wait_group 0;" ::: "memory");
        __syncthreads();

        float acc[2][2][4];
#pragma unroll
        for (int mi = 0; mi < 2; mi++)
#pragma unroll
            for (int ni = 0; ni < 2; ni++)
#pragma unroll
                for (int q = 0; q < 4; q++) acc[mi][ni][q] = 0.f;

#pragma unroll
        for (int kt = 0; kt < 16; kt++) {
            int cc = kt * 16;
            uint32_t a[2][4], b[2][2];
#pragma unroll
            for (int mi = 0; mi < 2; mi++) {
                int r = wm * 32 + mi * 16 + (lane & 15);
                int col = cc + ((lane >> 4) << 3);
                ldsm_x4(a[mi][0], a[mi][1], a[mi][2], a[mi][3],
                        sa + (uint32_t)(r * QA_LD + col) * 2u);
            }
            {
                int n = wn * 16 + ((lane >> 4) & 1) * 8 + (lane & 7);
                int colb = cc + ((lane >> 3) & 1) * 8;
                ldsm_x4(b[0][0], b[0][1], b[1][0], b[1][1],
                        sbB + (uint32_t)(n * QA_LD + colb) * 2u);
            }
#pragma unroll
            for (int mi = 0; mi < 2; mi++)
#pragma unroll
                for (int ni = 0; ni < 2; ni++)
                    mma_bf16(acc[mi][ni], a[mi][0], a[mi][1], a[mi][2], a[mi][3],
                             b[ni][0], b[ni][1]);
        }
        // fold W[r,cl] * x[r,cl] into per-row partials
#pragma unroll
        for (int mi = 0; mi < 2; mi++)
#pragma unroll
            for (int h = 0; h < 2; h++) {
                int r = wm * 32 + mi * 16 + (lane >> 2) + 8 * h;
                float p = 0.f;
#pragma unroll
                for (int ni = 0; ni < 2; ni++)
#pragma unroll
                    for (int w = 0; w < 2; w++) {
                        int cl = nb * 64 + wn * 16 + ni * 8 + 2 * (lane & 3) + w;
                        p = fmaf(acc[mi][ni][2 * h + w],
                                 __bfloat162float(smA[r * QA_LD + cl]), p);
                    }
                s2[mi][h] += p;
            }
    }
#pragma unroll
    for (int mi = 0; mi < 2; mi++)
#pragma unroll
        for (int h = 0; h < 2; h++) {
            float p = s2[mi][h];
            p += __shfl_xor_sync(~0u, p, 1);
            p += __shfl_xor_sync(~0u, p, 2);
            if ((lane & 3) == 0)
                atomicAdd(&sRow[wm * 32 + mi * 16 + (lane >> 2) + 8 * h], p);
        }
    __syncthreads();
    if (tid < 64) OUT[rb * 64 + tid] = sRow[tid];

    // ---- S1: row dot v (thread = (row r, quarter q)); smA/sV both resident ----
    {
        int r = tid & 63, q = tid >> 6;
        float s1p = 0.f;
#pragma unroll 16
        for (int k = 0; k < 64; k++) {
            int cl = q * 64 + k;
            s1p = fmaf(__bfloat162float(smA[r * QA_LD + cl]), sV[cl], s1p);
        }
        sS1[q * 64 + r] = s1p;
    }
    __syncthreads();
    if (tid < 64)
        OUT1[rb * 64 + tid] = sS1[tid] + sS1[64 + tid] + sS1[128 + tid] + sS1[192 + tid];
}

// ---------------- finalize: scalar per row (R10 exact) ----------------
__device__ __forceinline__ float half_loss(float s1, float s2, float d) {
    float r = sqrtf(fmaxf(s2, 1e-24f));
    float a = 1.0f / r;
    float t = a * d;
    float off = (float)NN + a * s1 + 0.5f - (1.0f + t + 0.5f * t * t);
    float num = t - 0.4f;
    float den = expf(num) + off;
    return num - logf(den);
}

__global__ void finalize_kernel(float* __restrict__ out) {
    const int i = blockIdx.x * 256 + threadIdx.x;   // 32 blocks x 256 = 8192
    float d = g_d[i];
    float l12 = half_loss(g_S1r[i], g_S2r[i], d);
    float l21 = half_loss(g_S1c[i], g_S2c[i], d);
    out[1 + i]      = l12;
    out[1 + NN + i] = l21;
    float v = l12 + l21;
#pragma unroll
    for (int o = 16; o; o >>= 1) v += __shfl_xor_sync(~0u, v, o);
    __shared__ float ws[8];
    if ((threadIdx.x & 31) == 0) ws[threadIdx.x >> 5] = v;
    __syncthreads();
    if (threadIdx.x == 0) {
        float t = 0.f;
#pragma unroll
        for (int k = 0; k < 8; k++) t += ws[k];
        atomicAdd(&g_lsum, t);
        __threadfence();
        unsigned tk = atomicAdd(&g_tkf, 1u);
        if (tk == gridDim.x - 1)                        // last block: full sum present
            out[0] = -atomicAdd(&g_lsum, 0.0f) / (float)NN;
    }
}

extern "C" void kernel_launch(void* const* d_in, const int* in_sizes, int n_in,
                              void* d_out, int out_size) {
    const float* x1 = (const float*)d_in[0];
    const float* x2 = (const float*)d_in[1];
    float* out = (float*)d_out;

    cudaFuncSetAttribute(quad_kernel, cudaFuncAttributeMaxDynamicSharedMemorySize, SMEM_Q);

    prep_kernel<<<256, 256>>>(x1, x2);
    syrk_kernel<<<dim3(32, 4, 2), 256>>>();
    cvt_kernel<<<130, 256>>>();
    quad_kernel<<<dim3(128, 2), 256, SMEM_Q>>>();
    finalize_kernel<<<32, 256>>>(out);
}

// round 14
// speedup vs baseline: 1.1163x; 1.1163x over previous
#include <cuda_runtime.h>
#include <cuda_bf16.h>
#include <math.h>
#include <stdint.h>

#define NN 8192
#define DD 256

// ---------------- device scratch (every array overwritten or reset each replay) ----------------
__device__ __align__(16) __nv_bfloat16 g_Ab[NN * DD];   // x1 bf16
__device__ __align__(16) __nv_bfloat16 g_Bb[NN * DD];   // x2 bf16
__device__ float g_Cf[DD * DD];    // x2^T x2 (fp32 accum; zeroed by prep each replay)
__device__ float g_Bf[DD * DD];    // x1^T x1
__device__ __align__(16) __nv_bfloat16 g_Cfb[DD * DD];  // bf16 copies for quad
__device__ __align__(16) __nv_bfloat16 g_Bfb[DD * DD];
__device__ float g_v1p[256 * 256], g_v2p[256 * 256];    // per-block column-sum partials
__device__ float g_v1[DD], g_v2[DD];                    // written by cvt (plain store)
__device__ float g_d[NN];                               // exact fp32 diagonal, written by prep
__device__ float g_S1r[NN], g_S1c[NN];                  // written by quad
__device__ float g_S2r[NN], g_S2c[NN];                  // written by quad
__device__ float g_lsum;                                // reset by cvt each replay
__device__ unsigned g_tkf;                              // reset by cvt each replay

// ---------------- prep: f32->bf16, v-partials, exact diagonal, zero Gram (R10 exact) ----------------
__global__ void prep_kernel(const float* __restrict__ x1, const float* __restrict__ x2) {
    __shared__ float sd[32][257];
    const int t = threadIdx.x;            // column 0..255
    const int b = blockIdx.x;
    const int r0 = b * 32;
    float v1 = 0.f, v2 = 0.f;
#pragma unroll 4
    for (int r = 0; r < 32; r++) {
        int idx = (r0 + r) * DD + t;
        float f1 = x1[idx], f2 = x2[idx];
        g_Ab[idx] = __float2bfloat16(f1);
        g_Bb[idx] = __float2bfloat16(f2);
        v1 += f1;
        v2 += f2;
        sd[r][t] = f1 * f2;
    }
    g_v1p[b * 256 + t] = v1;              // plain store, no pre-zero needed
    g_v2p[b * 256 + t] = v2;
    int i = b * 256 + t;                  // covers 65536 = DD*DD
    g_Cf[i] = 0.f;
    g_Bf[i] = 0.f;
    __syncthreads();
    const int warp = t >> 5, lane = t & 31;
#pragma unroll
    for (int rr = 0; rr < 4; rr++) {      // warp w reduces rows 4w..4w+3
        int row = warp * 4 + rr;
        float s = 0.f;
#pragma unroll
        for (int k = lane; k < 256; k += 32) s += sd[row][k];
#pragma unroll
        for (int o = 16; o; o >>= 1) s += __shfl_xor_sync(~0u, s, o);
        if (lane == 0) g_d[r0 + row] = s;
    }
}

// ---------------- PTX helpers ----------------
__device__ __forceinline__ void cp_async16(uint32_t dst, const void* src) {
    asm volatile("cp.async.cg.shared.global [%0], [%1], 16;" :: "r"(dst), "l"(src));
}
__device__ __forceinline__ void ldsm_x4(uint32_t& r0, uint32_t& r1, uint32_t& r2, uint32_t& r3,
                                        uint32_t addr) {
    asm volatile("ldmatrix.sync.aligned.m8n8.x4.shared.b16 {%0,%1,%2,%3}, [%4];"
                 : "=r"(r0), "=r"(r1), "=r"(r2), "=r"(r3) : "r"(addr));
}
__device__ __forceinline__ void ldsm_x4_t(uint32_t& r0, uint32_t& r1, uint32_t& r2, uint32_t& r3,
                                          uint32_t addr) {
    asm volatile("ldmatrix.sync.aligned.m8n8.x4.trans.shared.b16 {%0,%1,%2,%3}, [%4];"
                 : "=r"(r0), "=r"(r1), "=r"(r2), "=r"(r3) : "r"(addr));
}
__device__ __forceinline__ void mma_bf16(float c[4], uint32_t a0, uint32_t a1, uint32_t a2,
                                         uint32_t a3, uint32_t b0, uint32_t b1) {
    asm volatile("mma.sync.aligned.m16n8k16.row.col.f32.bf16.bf16.f32 "
                 "{%0,%1,%2,%3}, {%4,%5,%6,%7}, {%8,%9}, {%0,%1,%2,%3};"
                 : "+f"(c[0]), "+f"(c[1]), "+f"(c[2]), "+f"(c[3])
                 : "r"(a0), "r"(a1), "r"(a2), "r"(a3), "r"(b0), "r"(b1));
}

// ---------------- syrk: 128x64 tiles, 16 K-splits, 3 CTAs/SM (halved atomics) ----------------
// grid: x = 16 K-chunks (512 rows each), y = 8 tiles (ta row-half, tb col-quarter), z = 2
#define SK_LD 200                   // 400B row: 25x16B, 25 % 8 = 1 -> conflict-free ldmatrix
#define SK_STAGE (32 * SK_LD)       // elems per stage

__global__ void __launch_bounds__(256, 3) syrk_kernel() {
    __shared__ __nv_bfloat16 sm[2 * SK_STAGE];
    uint32_t sb = (uint32_t)__cvta_generic_to_shared(sm);
    const int tid = threadIdx.x, lane = tid & 31, warp = tid >> 5;
    const int wm = warp >> 2, wn = warp & 3;
    const int ta = blockIdx.y >> 2;          // 0..1 : rows ta*128
    const int tb = blockIdx.y & 3;           // 0..3 : cols tb*64
    const __nv_bfloat16* X = blockIdx.z ? g_Ab : g_Bb;
    float* OUT = blockIdx.z ? g_Bf : g_Cf;
    const int r0 = blockIdx.x * 512;

    float acc[4][2][4];
#pragma unroll
    for (int mi = 0; mi < 4; mi++)
#pragma unroll
        for (int ni = 0; ni < 2; ni++)
#pragma unroll
            for (int q = 0; q < 4; q++) acc[mi][ni][q] = 0.f;

    auto load_stage = [&](int kt, int buf) {
#pragma unroll
        for (int i = 0; i < 3; i++) {             // 768 chunks of 16B = 32 rows x 24 chunks
            int c = tid + i * 256;
            int row = c / 24, sub = c % 24;       // 16 A-chunks + 8 B-chunks per row
            int gcol = (sub < 16) ? ta * 128 + sub * 8 : tb * 64 + (sub - 16) * 8;
            cp_async16(sb + (uint32_t)(buf * SK_STAGE + row * SK_LD + sub * 8) * 2u,
                       X + (size_t)(r0 + kt * 32 + row) * DD + gcol);
        }
    };

    load_stage(0, 0);
    asm volatile("cp.async.commit_group;" ::: "memory");
    for (int kt = 0; kt < 16; kt++) {
        const int buf = kt & 1;
        if (kt < 15) {
            load_stage(kt + 1, buf ^ 1);
            asm volatile("cp.async.commit_group;" ::: "memory");
            asm volatile("cp.async.wait_group 1;" ::: "memory");
        } else {
            asm volatile("cp.async.wait_group 0;" ::: "memory");
        }
        __syncthreads();
        uint32_t base = sb + (uint32_t)(buf * SK_STAGE) * 2u;
#pragma unroll
        for (int kk = 0; kk < 32; kk += 16) {
            uint32_t a[4][4], b[2][2];
            int krA = kk + (lane & 7) + ((lane >> 4) & 1) * 8;
            int mofA = ((lane >> 3) & 1) * 8;
#pragma unroll
            for (int mi = 0; mi < 4; mi++) {
                int m = wm * 64 + mi * 16 + mofA;
                ldsm_x4_t(a[mi][0], a[mi][1], a[mi][2], a[mi][3],
                          base + (uint32_t)(krA * SK_LD + m) * 2u);
            }
            int krB = kk + (lane & 7) + ((lane >> 3) & 1) * 8;
            int nofB = ((lane >> 4) & 1) * 8;
            {
                int n = 128 + wn * 16 + nofB;
                ldsm_x4_t(b[0][0], b[0][1], b[1][0], b[1][1],
                          base + (uint32_t)(krB * SK_LD + n) * 2u);
            }
#pragma unroll
            for (int mi = 0; mi < 4; mi++)
#pragma unroll
                for (int ni = 0; ni < 2; ni++)
                    mma_bf16(acc[mi][ni], a[mi][0], a[mi][1], a[mi][2], a[mi][3],
                             b[ni][0], b[ni][1]);
        }
        __syncthreads();
    }

#pragma unroll
    for (int mi = 0; mi < 4; mi++)
#pragma unroll
        for (int ni = 0; ni < 2; ni++)
#pragma unroll
            for (int h = 0; h < 2; h++)
#pragma unroll
                for (int w = 0; w < 2; w++) {
                    int gm = ta * 128 + wm * 64 + mi * 16 + (lane >> 2) + 8 * h;
                    int gn = tb * 64 + wn * 16 + ni * 8 + 2 * (lane & 3) + w;
                    atomicAdd(&OUT[gm * DD + gn], acc[mi][ni][2 * h + w]);
                }
}

// ---------------- cvt: Gram fp32->bf16 (128 blocks) + PARALLEL v-reduction (64 blocks) ----------------
__global__ void cvt_kernel() {
    const int bid = blockIdx.x, t = threadIdx.x;
    if (bid < 128) {
        int i = (bid * 256 + t) * 2;
        float2 c = *(const float2*)(g_Cf + i);
        float2 b = *(const float2*)(g_Bf + i);
        *(__nv_bfloat162*)(g_Cfb + i) = __floats2bfloat162_rn(c.x, c.y);
        *(__nv_bfloat162*)(g_Bfb + i) = __floats2bfloat162_rn(b.x, b.y);
    } else {
        // blocks 128..159: v1 (32 blocks x 8 cols); 160..191: v2
        const int rb = bid - 128;
        const float* P = (rb < 32) ? g_v1p : g_v2p;
        float* V = (rb < 32) ? g_v1 : g_v2;
        const int base = (rb & 31) * 8;
        const int warp = t >> 5, lane = t & 31;
        const int col = base + warp;               // 8 warps -> 8 columns
        float s = 0.f;
#pragma unroll
        for (int u = 0; u < 8; u++)                // lane covers rows lane*8+u
            s += P[(lane * 8 + u) * 256 + col];
#pragma unroll
        for (int o = 16; o; o >>= 1) s += __shfl_xor_sync(~0u, s, o);
        if (lane == 0) V[col] = s;
        if (bid == 191 && t == 0) { g_lsum = 0.f; g_tkf = 0u; }   // before finalize, each replay
    }
}

// ---------------- quad: S2 + S1 per row (R10 exact, 14.8us proven) ----------------
// grid: x = 128 row-blocks of 64 rows, y = 2 matrices; 2 CTAs/SM
#define QA_LD 264
#define SMA_ELEMS (64 * QA_LD)
#define SMB_ELEMS (128 * QA_LD)
#define SMEM_Q ((SMA_ELEMS + SMB_ELEMS) * 2 + (64 + 256 + 256) * 4)

__global__ void __launch_bounds__(256, 2) quad_kernel() {
    extern __shared__ char qs[];
    __nv_bfloat16* smA = (__nv_bfloat16*)qs;
    __nv_bfloat16* smB = smA + SMA_ELEMS;
    float* sRow = (float*)(qs + (SMA_ELEMS + SMB_ELEMS) * 2);
    float* sS1  = sRow + 64;
    float* sV   = sS1 + 256;
    uint32_t sa = (uint32_t)__cvta_generic_to_shared(smA);
    uint32_t sbB = (uint32_t)__cvta_generic_to_shared(smB);
    const int tid = threadIdx.x, lane = tid & 31, warp = tid >> 5;
    const int wm = warp >> 2, wn = warp & 3;   // wm 0..1 (32 rows), wn 0..3 (32 cols)
    const int rb = blockIdx.x;
    const __nv_bfloat16* A = blockIdx.y ? g_Bb : g_Ab;
    const __nv_bfloat16* Cb = blockIdx.y ? g_Bfb : g_Cfb;
    const float* Vsrc = blockIdx.y ? g_v1 : g_v2;
    float* OUT  = blockIdx.y ? g_S2c : g_S2r;
    float* OUT1 = blockIdx.y ? g_S1c : g_S1r;

    // A tile 64x256 resident (2048 chunks of 16B)
#pragma unroll
    for (int i = 0; i < 8; i++) {
        int c = tid + i * 256;
        int row = c >> 5, col8 = c & 31;
        cp_async16(sa + (uint32_t)(row * QA_LD + col8 * 8) * 2u,
                   A + (size_t)(rb * 64 + row) * DD + col8 * 8);
    }
    asm volatile("cp.async.commit_group;" ::: "memory");
    if (tid < 64) sRow[tid] = 0.f;
    sV[tid] = Vsrc[tid];

    float s2[2][2];
    s2[0][0] = s2[0][1] = s2[1][0] = s2[1][1] = 0.f;

    for (int nb = 0; nb < 2; nb++) {
        if (nb) __syncthreads();   // smB safe to overwrite
        // B half: C rows nb*128 .. +128 = 4096 chunks of 16B
#pragma unroll
        for (int i = 0; i < 16; i++) {
            int c = tid + i * 256;
            int row = c >> 5, col8 = c & 31;
            cp_async16(sbB + (uint32_t)(row * QA_LD + col8 * 8) * 2u,
                       Cb + (size_t)(nb * 128 + row) * DD + col8 * 8);
        }
        asm volatile("cp.async.commit_group;" ::: "memory");
        asm volatile("cp.async.wait_group 0;" ::: "memory");
        __syncthreads();

        float acc[2][4][4];
#pragma unroll
        for (int mi = 0; mi < 2; mi++)
#pragma unroll
            for (int ni = 0; ni < 4; ni++)
#pragma unroll
                for (int q = 0; q < 4; q++) acc[mi][ni][q] = 0.f;

#pragma unroll
        for (int kt = 0; kt < 16; kt++) {
            int cc = kt * 16;
            uint32_t a[2][4], b[4][2];
#pragma unroll
            for (int mi = 0; mi < 2; mi++) {
                int r = wm * 32 + mi * 16 + (lane & 15);
                int col = cc + ((lane >> 4) << 3);
                ldsm_x4(a[mi][0], a[mi][1], a[mi][2], a[mi][3],
                        sa + (uint32_t)(r * QA_LD + col) * 2u);
            }
#pragma unroll
            for (int j = 0; j < 2; j++) {
                int n = wn * 32 + j * 16 + ((lane >> 4) & 1) * 8 + (lane & 7);
                int colb = cc + ((lane >> 3) & 1) * 8;
                ldsm_x4(b[2 * j][0], b[2 * j][1], b[2 * j + 1][0], b[2 * j + 1][1],
                        sbB + (uint32_t)(n * QA_LD + colb) * 2u);
            }
#pragma unroll
            for (int mi = 0; mi < 2; mi++)
#pragma unroll
                for (int ni = 0; ni < 4; ni++)
                    mma_bf16(acc[mi][ni], a[mi][0], a[mi][1], a[mi][2], a[mi][3],
                             b[ni][0], b[ni][1]);
        }
        // fold W[r,cl] * x[r,cl] into per-row partials
#pragma unroll
        for (int mi = 0; mi < 2; mi++)
#pragma unroll
            for (int h = 0; h < 2; h++) {
                int r = wm * 32 + mi * 16 + (lane >> 2) + 8 * h;
                float p = 0.f;
#pragma unroll
                for (int ni = 0; ni < 4; ni++)
#pragma unroll
                    for (int w = 0; w < 2; w++) {
                        int cl = nb * 128 + wn * 32 + ni * 8 + 2 * (lane & 3) + w;
                        p = fmaf(acc[mi][ni][2 * h + w],
                                 __bfloat162float(smA[r * QA_LD + cl]), p);
                    }
                s2[mi][h] += p;
            }
    }
#pragma unroll
    for (int mi = 0; mi < 2; mi++)
#pragma unroll
        for (int h = 0; h < 2; h++) {
            float p = s2[mi][h];
            p += __shfl_xor_sync(~0u, p, 1);
            p += __shfl_xor_sync(~0u, p, 2);
            if ((lane & 3) == 0)
                atomicAdd(&sRow[wm * 32 + mi * 16 + (lane >> 2) + 8 * h], p);
        }
    __syncthreads();
    if (tid < 64) OUT[rb * 64 + tid] = sRow[tid];

    // ---- S1: row dot v (thread = (row r, quarter q)); smA/sV both resident ----
    {
        int r = tid & 63, q = tid >> 6;
        float s1p = 0.f;
#pragma unroll 16
        for (int k = 0; k < 64; k++) {
            int cl = q * 64 + k;
            s1p = fmaf(__bfloat162float(smA[r * QA_LD + cl]), sV[cl], s1p);
        }
        sS1[q * 64 + r] = s1p;
    }
    __syncthreads();
    if (tid < 64)
        OUT1[rb * 64 + tid] = sS1[tid] + sS1[64 + tid] + sS1[128 + tid] + sS1[192 + tid];
}

// ---------------- finalize: scalar per row (R10 exact) ----------------
__device__ __forceinline__ float half_loss(float s1, float s2, float d) {
    float r = sqrtf(fmaxf(s2, 1e-24f));
    float a = 1.0f / r;
    float t = a * d;
    float off = (float)NN + a * s1 + 0.5f - (1.0f + t + 0.5f * t * t);
    float num = t - 0.4f;
    float den = expf(num) + off;
    return num - logf(den);
}

__global__ void finalize_kernel(float* __restrict__ out) {
    const int i = blockIdx.x * 256 + threadIdx.x;   // 32 blocks x 256 = 8192
    float d = g_d[i];
    float l12 = half_loss(g_S1r[i], g_S2r[i], d);
    float l21 = half_loss(g_S1c[i], g_S2c[i], d);
    out[1 + i]      = l12;
    out[1 + NN + i] = l21;
    float v = l12 + l21;
#pragma unroll
    for (int o = 16; o; o >>= 1) v += __shfl_xor_sync(~0u, v, o);
    __shared__ float ws[8];
    if ((threadIdx.x & 31) == 0) ws[threadIdx.x >> 5] = v;
    __syncthreads();
    if (threadIdx.x == 0) {
        float t = 0.f;
#pragma unroll
        for (int k = 0; k < 8; k++) t += ws[k];
        atomicAdd(&g_lsum, t);
        __threadfence();
        unsigned tk = atomicAdd(&g_tkf, 1u);
        if (tk == gridDim.x - 1)                        // last block: full sum present
            out[0] = -atomicAdd(&g_lsum, 0.0f) / (float)NN;
    }
}

extern "C" void kernel_launch(void* const* d_in, const int* in_sizes, int n_in,
                              void* d_out, int out_size) {
    const float* x1 = (const float*)d_in[0];
    const float* x2 = (const float*)d_in[1];
    float* out = (float*)d_out;

    cudaFuncSetAttribute(quad_kernel, cudaFuncAttributeMaxDynamicSharedMemorySize, SMEM_Q);

    prep_kernel<<<256, 256>>>(x1, x2);
    syrk_kernel<<<dim3(16, 8, 2), 256>>>();
    cvt_kernel<<<192, 256>>>();
    quad_kernel<<<dim3(128, 2), 256, SMEM_Q>>>();
    finalize_kernel<<<32, 256>>>(out);
}

// round 15
// speedup vs baseline: 1.1171x; 1.0008x over previous
#include <cuda_runtime.h>
#include <cuda_bf16.h>
#include <math.h>
#include <stdint.h>

#define NN 8192
#define DD 256

// ---------------- device scratch (every array overwritten or reset each replay) ----------------
__device__ __align__(16) __nv_bfloat16 g_Ab[NN * DD];   // x1 bf16
__device__ __align__(16) __nv_bfloat16 g_Bb[NN * DD];   // x2 bf16
__device__ float g_Cf[DD * DD];    // x2^T x2 (fp32 accum; zeroed by prep each replay)
__device__ float g_Bf[DD * DD];    // x1^T x1
__device__ __align__(16) __nv_bfloat16 g_Cfb[DD * DD];  // bf16 copies for quad
__device__ __align__(16) __nv_bfloat16 g_Bfb[DD * DD];
__device__ float g_v1p[256 * 256], g_v2p[256 * 256];    // per-block column-sum partials
__device__ float g_v1[DD], g_v2[DD];                    // written by cvt (plain store)
__device__ float g_d[NN];                               // exact fp32 diagonal, written by prep
__device__ float g_S1r[NN], g_S1c[NN];                  // written by quad
__device__ float g_S2r[NN], g_S2c[NN];                  // written by quad
__device__ float g_lsum;                                // reset by cvt each replay
__device__ unsigned g_tkf;                              // reset by cvt each replay

// ---------------- prep: f32->bf16, v-partials, exact diagonal, zero Gram (R10 exact) ----------------
__global__ void prep_kernel(const float* __restrict__ x1, const float* __restrict__ x2) {
    __shared__ float sd[32][257];
    const int t = threadIdx.x;            // column 0..255
    const int b = blockIdx.x;
    const int r0 = b * 32;
    float v1 = 0.f, v2 = 0.f;
#pragma unroll 4
    for (int r = 0; r < 32; r++) {
        int idx = (r0 + r) * DD + t;
        float f1 = x1[idx], f2 = x2[idx];
        g_Ab[idx] = __float2bfloat16(f1);
        g_Bb[idx] = __float2bfloat16(f2);
        v1 += f1;
        v2 += f2;
        sd[r][t] = f1 * f2;
    }
    g_v1p[b * 256 + t] = v1;              // plain store, no pre-zero needed
    g_v2p[b * 256 + t] = v2;
    int i = b * 256 + t;                  // covers 65536 = DD*DD
    g_Cf[i] = 0.f;
    g_Bf[i] = 0.f;
    __syncthreads();
    const int warp = t >> 5, lane = t & 31;
#pragma unroll
    for (int rr = 0; rr < 4; rr++) {      // warp w reduces rows 4w..4w+3
        int row = warp * 4 + rr;
        float s = 0.f;
#pragma unroll
        for (int k = lane; k < 256; k += 32) s += sd[row][k];
#pragma unroll
        for (int o = 16; o; o >>= 1) s += __shfl_xor_sync(~0u, s, o);
        if (lane == 0) g_d[r0 + row] = s;
    }
}

// ---------------- PTX helpers ----------------
__device__ __forceinline__ void cp_async16(uint32_t dst, const void* src) {
    asm volatile("cp.async.cg.shared.global [%0], [%1], 16;" :: "r"(dst), "l"(src));
}
__device__ __forceinline__ void ldsm_x4(uint32_t& r0, uint32_t& r1, uint32_t& r2, uint32_t& r3,
                                        uint32_t addr) {
    asm volatile("ldmatrix.sync.aligned.m8n8.x4.shared.b16 {%0,%1,%2,%3}, [%4];"
                 : "=r"(r0), "=r"(r1), "=r"(r2), "=r"(r3) : "r"(addr));
}
__device__ __forceinline__ void ldsm_x4_t(uint32_t& r0, uint32_t& r1, uint32_t& r2, uint32_t& r3,
                                          uint32_t addr) {
    asm volatile("ldmatrix.sync.aligned.m8n8.x4.trans.shared.b16 {%0,%1,%2,%3}, [%4];"
                 : "=r"(r0), "=r"(r1), "=r"(r2), "=r"(r3) : "r"(addr));
}
__device__ __forceinline__ void mma_bf16(float c[4], uint32_t a0, uint32_t a1, uint32_t a2,
                                         uint32_t a3, uint32_t b0, uint32_t b1) {
    asm volatile("mma.sync.aligned.m16n8k16.row.col.f32.bf16.bf16.f32 "
                 "{%0,%1,%2,%3}, {%4,%5,%6,%7}, {%8,%9}, {%0,%1,%2,%3};"
                 : "+f"(c[0]), "+f"(c[1]), "+f"(c[2]), "+f"(c[3])
                 : "r"(a0), "r"(a1), "r"(a2), "r"(a3), "r"(b0), "r"(b1));
}

// ---------------- syrk: 128x64 tiles, 16 K-splits, 3 CTAs/SM, 64-row stages ----------------
// grid: x = 16 K-chunks (512 rows each), y = 8 tiles (ta row-half, tb col-quarter), z = 2
#define SK_LD 200                   // 400B row: 25x16B, 25 % 8 = 1 -> conflict-free ldmatrix
#define SK_ROWS 64                  // rows per stage
#define SK_STAGE (SK_ROWS * SK_LD)  // elems per stage (2 stages = 51.2 KB)

__global__ void __launch_bounds__(256, 3) syrk_kernel() {
    __shared__ __nv_bfloat16 sm[2 * SK_STAGE];
    uint32_t sb = (uint32_t)__cvta_generic_to_shared(sm);
    const int tid = threadIdx.x, lane = tid & 31, warp = tid >> 5;
    const int wm = warp >> 2, wn = warp & 3;
    const int ta = blockIdx.y >> 2;          // 0..1 : rows ta*128
    const int tb = blockIdx.y & 3;           // 0..3 : cols tb*64
    const __nv_bfloat16* X = blockIdx.z ? g_Ab : g_Bb;
    float* OUT = blockIdx.z ? g_Bf : g_Cf;
    const int r0 = blockIdx.x * 512;

    float acc[4][2][4];
#pragma unroll
    for (int mi = 0; mi < 4; mi++)
#pragma unroll
        for (int ni = 0; ni < 2; ni++)
#pragma unroll
            for (int q = 0; q < 4; q++) acc[mi][ni][q] = 0.f;

    auto load_stage = [&](int kt, int buf) {
#pragma unroll
        for (int i = 0; i < 6; i++) {             // 1536 chunks = 64 rows x 24 chunks
            int c = tid + i * 256;
            int row = c / 24, sub = c % 24;       // 16 A-chunks + 8 B-chunks per row
            int gcol = (sub < 16) ? ta * 128 + sub * 8 : tb * 64 + (sub - 16) * 8;
            cp_async16(sb + (uint32_t)(buf * SK_STAGE + row * SK_LD + sub * 8) * 2u,
                       X + (size_t)(r0 + kt * SK_ROWS + row) * DD + gcol);
        }
    };

    load_stage(0, 0);
    asm volatile("cp.async.commit_group;" ::: "memory");
    for (int kt = 0; kt < 8; kt++) {
        const int buf = kt & 1;
        if (kt < 7) {
            load_stage(kt + 1, buf ^ 1);
            asm volatile("cp.async.commit_group;" ::: "memory");
            asm volatile("cp.async.wait_group 1;" ::: "memory");
        } else {
            asm volatile("cp.async.wait_group 0;" ::: "memory");
        }
        __syncthreads();
        uint32_t base = sb + (uint32_t)(buf * SK_STAGE) * 2u;
#pragma unroll
        for (int kk = 0; kk < SK_ROWS; kk += 16) {
            uint32_t a[4][4], b[2][2];
            int krA = kk + (lane & 7) + ((lane >> 4) & 1) * 8;
            int mofA = ((lane >> 3) & 1) * 8;
#pragma unroll
            for (int mi = 0; mi < 4; mi++) {
                int m = wm * 64 + mi * 16 + mofA;
                ldsm_x4_t(a[mi][0], a[mi][1], a[mi][2], a[mi][3],
                          base + (uint32_t)(krA * SK_LD + m) * 2u);
            }
            int krB = kk + (lane & 7) + ((lane >> 3) & 1) * 8;
            int nofB = ((lane >> 4) & 1) * 8;
            {
                int n = 128 + wn * 16 + nofB;
                ldsm_x4_t(b[0][0], b[0][1], b[1][0], b[1][1],
                          base + (uint32_t)(krB * SK_LD + n) * 2u);
            }
#pragma unroll
            for (int mi = 0; mi < 4; mi++)
#pragma unroll
                for (int ni = 0; ni < 2; ni++)
                    mma_bf16(acc[mi][ni], a[mi][0], a[mi][1], a[mi][2], a[mi][3],
                             b[ni][0], b[ni][1]);
        }
        __syncthreads();
    }

#pragma unroll
    for (int mi = 0; mi < 4; mi++)
#pragma unroll
        for (int ni = 0; ni < 2; ni++)
#pragma unroll
            for (int h = 0; h < 2; h++)
#pragma unroll
                for (int w = 0; w < 2; w++) {
                    int gm = ta * 128 + wm * 64 + mi * 16 + (lane >> 2) + 8 * h;
                    int gn = tb * 64 + wn * 16 + ni * 8 + 2 * (lane & 3) + w;
                    atomicAdd(&OUT[gm * DD + gn], acc[mi][ni][2 * h + w]);
                }
}

// ---------------- cvt: Gram fp32->bf16 (128 blocks) + parallel v-reduction (64 blocks) ----------------
__global__ void cvt_kernel() {
    const int bid = blockIdx.x, t = threadIdx.x;
    if (bid < 128) {
        int i = (bid * 256 + t) * 2;
        float2 c = *(const float2*)(g_Cf + i);
        float2 b = *(const float2*)(g_Bf + i);
        *(__nv_bfloat162*)(g_Cfb + i) = __floats2bfloat162_rn(c.x, c.y);
        *(__nv_bfloat162*)(g_Bfb + i) = __floats2bfloat162_rn(b.x, b.y);
    } else {
        // blocks 128..159: v1 (32 blocks x 8 cols); 160..191: v2
        const int rb = bid - 128;
        const float* P = (rb < 32) ? g_v1p : g_v2p;
        float* V = (rb < 32) ? g_v1 : g_v2;
        const int base = (rb & 31) * 8;
        const int warp = t >> 5, lane = t & 31;
        const int col = base + warp;               // 8 warps -> 8 columns
        float s = 0.f;
#pragma unroll
        for (int u = 0; u < 8; u++)                // lane covers rows lane*8+u
            s += P[(lane * 8 + u) * 256 + col];
#pragma unroll
        for (int o = 16; o; o >>= 1) s += __shfl_xor_sync(~0u, s, o);
        if (lane == 0) V[col] = s;
        if (bid == 191 && t == 0) { g_lsum = 0.f; g_tkf = 0u; }   // before finalize, each replay
    }
}

// ---------------- quad: S2 + S1 per row; fragment-pipelined mainloop ----------------
// grid: x = 128 row-blocks of 64 rows, y = 2 matrices; 2 CTAs/SM
#define QA_LD 264
#define SMA_ELEMS (64 * QA_LD)
#define SMB_ELEMS (128 * QA_LD)
#define SMEM_Q ((SMA_ELEMS + SMB_ELEMS) * 2 + (64 + 256 + 256) * 4)

__global__ void __launch_bounds__(256, 2) quad_kernel() {
    extern __shared__ char qs[];
    __nv_bfloat16* smA = (__nv_bfloat16*)qs;
    __nv_bfloat16* smB = smA + SMA_ELEMS;
    float* sRow = (float*)(qs + (SMA_ELEMS + SMB_ELEMS) * 2);
    float* sS1  = sRow + 64;
    float* sV   = sS1 + 256;
    uint32_t sa = (uint32_t)__cvta_generic_to_shared(smA);
    uint32_t sbB = (uint32_t)__cvta_generic_to_shared(smB);
    const int tid = threadIdx.x, lane = tid & 31, warp = tid >> 5;
    const int wm = warp >> 2, wn = warp & 3;   // wm 0..1 (32 rows), wn 0..3 (32 cols)
    const int rb = blockIdx.x;
    const __nv_bfloat16* A = blockIdx.y ? g_Bb : g_Ab;
    const __nv_bfloat16* Cb = blockIdx.y ? g_Bfb : g_Cfb;
    const float* Vsrc = blockIdx.y ? g_v1 : g_v2;
    float* OUT  = blockIdx.y ? g_S2c : g_S2r;
    float* OUT1 = blockIdx.y ? g_S1c : g_S1r;

    // A tile 64x256 resident (2048 chunks of 16B)
#pragma unroll
    for (int i = 0; i < 8; i++) {
        int c = tid + i * 256;
        int row = c >> 5, col8 = c & 31;
        cp_async16(sa + (uint32_t)(row * QA_LD + col8 * 8) * 2u,
                   A + (size_t)(rb * 64 + row) * DD + col8 * 8);
    }
    asm volatile("cp.async.commit_group;" ::: "memory");
    if (tid < 64) sRow[tid] = 0.f;
    sV[tid] = Vsrc[tid];

    float s2[2][2];
    s2[0][0] = s2[0][1] = s2[1][0] = s2[1][1] = 0.f;

    // per-thread ldsm address components (kt-invariant)
    const int rA0 = wm * 32 + (lane & 15);
    const int colA = (lane >> 4) << 3;
    const int nB  = wn * 32 + ((lane >> 4) & 1) * 8 + (lane & 7);
    const int colB = ((lane >> 3) & 1) * 8;

    for (int nb = 0; nb < 2; nb++) {
        if (nb) __syncthreads();   // smB safe to overwrite
        // B half: C rows nb*128 .. +128 = 4096 chunks of 16B
#pragma unroll
        for (int i = 0; i < 16; i++) {
            int c = tid + i * 256;
            int row = c >> 5, col8 = c & 31;
            cp_async16(sbB + (uint32_t)(row * QA_LD + col8 * 8) * 2u,
                       Cb + (size_t)(nb * 128 + row) * DD + col8 * 8);
        }
        asm volatile("cp.async.commit_group;" ::: "memory");
        asm volatile("cp.async.wait_group 0;" ::: "memory");
        __syncthreads();

        float acc[2][4][4];
#pragma unroll
        for (int mi = 0; mi < 2; mi++)
#pragma unroll
            for (int ni = 0; ni < 4; ni++)
#pragma unroll
                for (int q = 0; q < 4; q++) acc[mi][ni][q] = 0.f;

        // fragment double-buffer: load kt+1 while mma'ing kt
        uint32_t a[2][2][4], b[2][4][2];
        auto load_frags = [&](int cc, uint32_t af[2][4], uint32_t bf[4][2]) {
#pragma unroll
            for (int mi = 0; mi < 2; mi++)
                ldsm_x4(af[mi][0], af[mi][1], af[mi][2], af[mi][3],
                        sa + (uint32_t)((rA0 + mi * 16) * QA_LD + cc + colA) * 2u);
#pragma unroll
            for (int j = 0; j < 2; j++)
                ldsm_x4(bf[2 * j][0], bf[2 * j][1], bf[2 * j + 1][0], bf[2 * j + 1][1],
                        sbB + (uint32_t)((nB + j * 16) * QA_LD + cc + colB) * 2u);
        };

        load_frags(0, a[0], b[0]);
#pragma unroll
        for (int kt = 0; kt < 16; kt++) {
            const int cur = kt & 1;
            if (kt < 15) load_frags((kt + 1) * 16, a[cur ^ 1], b[cur ^ 1]);
#pragma unroll
            for (int mi = 0; mi < 2; mi++)
#pragma unroll
                for (int ni = 0; ni < 4; ni++)
                    mma_bf16(acc[mi][ni], a[cur][mi][0], a[cur][mi][1], a[cur][mi][2],
                             a[cur][mi][3], b[cur][ni][0], b[cur][ni][1]);
        }
        // fold W[r,cl] * x[r,cl] into per-row partials
#pragma unroll
        for (int mi = 0; mi < 2; mi++)
#pragma unroll
            for (int h = 0; h < 2; h++) {
                int r = wm * 32 + mi * 16 + (lane >> 2) + 8 * h;
                float p = 0.f;
#pragma unroll
                for (int ni = 0; ni < 4; ni++)
#pragma unroll
                    for (int w = 0; w < 2; w++) {
                        int cl = nb * 128 + wn * 32 + ni * 8 + 2 * (lane & 3) + w;
                        p = fmaf(acc[mi][ni][2 * h + w],
                                 __bfloat162float(smA[r * QA_LD + cl]), p);
                    }
                s2[mi][h] += p;
            }
    }
#pragma unroll
    for (int mi = 0; mi < 2; mi++)
#pragma unroll
        for (int h = 0; h < 2; h++) {
            float p = s2[mi][h];
            p += __shfl_xor_sync(~0u, p, 1);
            p += __shfl_xor_sync(~0u, p, 2);
            if ((lane & 3) == 0)
                atomicAdd(&sRow[wm * 32 + mi * 16 + (lane >> 2) + 8 * h], p);
        }
    __syncthreads();
    if (tid < 64) OUT[rb * 64 + tid] = sRow[tid];

    // ---- S1: row dot v (thread = (row r, quarter q)); smA/sV both resident ----
    {
        int r = tid & 63, q = tid >> 6;
        float s1p = 0.f;
#pragma unroll 16
        for (int k = 0; k < 64; k++) {
            int cl = q * 64 + k;
            s1p = fmaf(__bfloat162float(smA[r * QA_LD + cl]), sV[cl], s1p);
        }
        sS1[q * 64 + r] = s1p;
    }
    __syncthreads();
    if (tid < 64)
        OUT1[rb * 64 + tid] = sS1[tid] + sS1[64 + tid] + sS1[128 + tid] + sS1[192 + tid];
}

// ---------------- finalize: scalar per row (R10 exact) ----------------
__device__ __forceinline__ float half_loss(float s1, float s2, float d) {
    float r = sqrtf(fmaxf(s2, 1e-24f));
    float a = 1.0f / r;
    float t = a * d;
    float off = (float)NN + a * s1 + 0.5f - (1.0f + t + 0.5f * t * t);
    float num = t - 0.4f;
    float den = expf(num) + off;
    return num - logf(den);
}

__global__ void finalize_kernel(float* __restrict__ out) {
    const int i = blockIdx.x * 256 + threadIdx.x;   // 32 blocks x 256 = 8192
    float d = g_d[i];
    float l12 = half_loss(g_S1r[i], g_S2r[i], d);
    float l21 = half_loss(g_S1c[i], g_S2c[i], d);
    out[1 + i]      = l12;
    out[1 + NN + i] = l21;
    float v = l12 + l21;
#pragma unroll
    for (int o = 16; o; o >>= 1) v += __shfl_xor_sync(~0u, v, o);
    __shared__ float ws[8];
    if ((threadIdx.x & 31) == 0) ws[threadIdx.x >> 5] = v;
    __syncthreads();
    if (threadIdx.x == 0) {
        float t = 0.f;
#pragma unroll
        for (int k = 0; k < 8; k++) t += ws[k];
        atomicAdd(&g_lsum, t);
        __threadfence();
        unsigned tk = atomicAdd(&g_tkf, 1u);
        if (tk == gridDim.x - 1)                        // last block: full sum present
            out[0] = -atomicAdd(&g_lsum, 0.0f) / (float)NN;
    }
}

extern "C" void kernel_launch(void* const* d_in, const int* in_sizes, int n_in,
                              void* d_out, int out_size) {
    const float* x1 = (const float*)d_in[0];
    const float* x2 = (const float*)d_in[1];
    float* out = (float*)d_out;

    cudaFuncSetAttribute(quad_kernel, cudaFuncAttributeMaxDynamicSharedMemorySize, SMEM_Q);

    prep_kernel<<<256, 256>>>(x1, x2);
    syrk_kernel<<<dim3(16, 8, 2), 256>>>();
    cvt_kernel<<<192, 256>>>();
    quad_kernel<<<dim3(128, 2), 256, SMEM_Q>>>();
    finalize_kernel<<<32, 256>>>(out);
}

// round 16
// speedup vs baseline: 1.1481x; 1.0278x over previous
#include <cuda_runtime.h>
#include <cuda_bf16.h>
#include <math.h>
#include <stdint.h>

#define NN 8192
#define DD 256

// ---------------- device scratch (every array overwritten or reset each replay) ----------------
__device__ __align__(16) __nv_bfloat16 g_Ab[NN * DD];   // x1 bf16
__device__ __align__(16) __nv_bfloat16 g_Bb[NN * DD];   // x2 bf16
__device__ float g_Cf[DD * DD];    // x2^T x2 (fp32 accum; zeroed by prep each replay)
__device__ float g_Bf[DD * DD];    // x1^T x1
__device__ uint2 g_Cfrag[32 * 16 * 32];   // C in mma B-fragment order (bf16), written by cvt
__device__ uint2 g_Bfrag[32 * 16 * 32];
__device__ float g_v1p[256 * 256], g_v2p[256 * 256];    // per-block column-sum partials
__device__ float g_v1[DD], g_v2[DD];                    // written by cvt (plain store)
__device__ float g_d[NN];                               // exact fp32 diagonal, written by prep
__device__ float g_S1r[NN], g_S1c[NN];                  // written by quad
__device__ float g_S2r[NN], g_S2c[NN];                  // written by quad
__device__ float g_lsum;                                // reset by cvt each replay
__device__ unsigned g_tkf;                              // reset by cvt each replay

// ---------------- prep: f32->bf16, v-partials, exact diagonal, zero Gram (R15 exact) ----------------
__global__ void prep_kernel(const float* __restrict__ x1, const float* __restrict__ x2) {
    __shared__ float sd[32][257];
    const int t = threadIdx.x;            // column 0..255
    const int b = blockIdx.x;
    const int r0 = b * 32;
    float v1 = 0.f, v2 = 0.f;
#pragma unroll 4
    for (int r = 0; r < 32; r++) {
        int idx = (r0 + r) * DD + t;
        float f1 = x1[idx], f2 = x2[idx];
        g_Ab[idx] = __float2bfloat16(f1);
        g_Bb[idx] = __float2bfloat16(f2);
        v1 += f1;
        v2 += f2;
        sd[r][t] = f1 * f2;
    }
    g_v1p[b * 256 + t] = v1;
    g_v2p[b * 256 + t] = v2;
    int i = b * 256 + t;                  // covers 65536 = DD*DD
    g_Cf[i] = 0.f;
    g_Bf[i] = 0.f;
    __syncthreads();
    const int warp = t >> 5, lane = t & 31;
#pragma unroll
    for (int rr = 0; rr < 4; rr++) {
        int row = warp * 4 + rr;
        float s = 0.f;
#pragma unroll
        for (int k = lane; k < 256; k += 32) s += sd[row][k];
#pragma unroll
        for (int o = 16; o; o >>= 1) s += __shfl_xor_sync(~0u, s, o);
        if (lane == 0) g_d[r0 + row] = s;
    }
}

// ---------------- PTX helpers ----------------
__device__ __forceinline__ void cp_async16(uint32_t dst, const void* src) {
    asm volatile("cp.async.cg.shared.global [%0], [%1], 16;" :: "r"(dst), "l"(src));
}
__device__ __forceinline__ void ldsm_x4(uint32_t& r0, uint32_t& r1, uint32_t& r2, uint32_t& r3,
                                        uint32_t addr) {
    asm volatile("ldmatrix.sync.aligned.m8n8.x4.shared.b16 {%0,%1,%2,%3}, [%4];"
                 : "=r"(r0), "=r"(r1), "=r"(r2), "=r"(r3) : "r"(addr));
}
__device__ __forceinline__ void ldsm_x4_t(uint32_t& r0, uint32_t& r1, uint32_t& r2, uint32_t& r3,
                                          uint32_t addr) {
    asm volatile("ldmatrix.sync.aligned.m8n8.x4.trans.shared.b16 {%0,%1,%2,%3}, [%4];"
                 : "=r"(r0), "=r"(r1), "=r"(r2), "=r"(r3) : "r"(addr));
}
__device__ __forceinline__ void mma_bf16(float c[4], uint32_t a0, uint32_t a1, uint32_t a2,
                                         uint32_t a3, uint32_t b0, uint32_t b1) {
    asm volatile("mma.sync.aligned.m16n8k16.row.col.f32.bf16.bf16.f32 "
                 "{%0,%1,%2,%3}, {%4,%5,%6,%7}, {%8,%9}, {%0,%1,%2,%3};"
                 : "+f"(c[0]), "+f"(c[1]), "+f"(c[2]), "+f"(c[3])
                 : "r"(a0), "r"(a1), "r"(a2), "r"(a3), "r"(b0), "r"(b1));
}

// ---------------- syrk: 128x64 tiles, 16 K-splits, 3 CTAs/SM, 64-row stages (R15 exact) ----------------
#define SK_LD 200
#define SK_ROWS 64
#define SK_STAGE (SK_ROWS * SK_LD)

__global__ void __launch_bounds__(256, 3) syrk_kernel() {
    __shared__ __nv_bfloat16 sm[2 * SK_STAGE];
    uint32_t sb = (uint32_t)__cvta_generic_to_shared(sm);
    const int tid = threadIdx.x, lane = tid & 31, warp = tid >> 5;
    const int wm = warp >> 2, wn = warp & 3;
    const int ta = blockIdx.y >> 2;
    const int tb = blockIdx.y & 3;
    const __nv_bfloat16* X = blockIdx.z ? g_Ab : g_Bb;
    float* OUT = blockIdx.z ? g_Bf : g_Cf;
    const int r0 = blockIdx.x * 512;

    float acc[4][2][4];
#pragma unroll
    for (int mi = 0; mi < 4; mi++)
#pragma unroll
        for (int ni = 0; ni < 2; ni++)
#pragma unroll
            for (int q = 0; q < 4; q++) acc[mi][ni][q] = 0.f;

    auto load_stage = [&](int kt, int buf) {
#pragma unroll
        for (int i = 0; i < 6; i++) {
            int c = tid + i * 256;
            int row = c / 24, sub = c % 24;
            int gcol = (sub < 16) ? ta * 128 + sub * 8 : tb * 64 + (sub - 16) * 8;
            cp_async16(sb + (uint32_t)(buf * SK_STAGE + row * SK_LD + sub * 8) * 2u,
                       X + (size_t)(r0 + kt * SK_ROWS + row) * DD + gcol);
        }
    };

    load_stage(0, 0);
    asm volatile("cp.async.commit_group;" ::: "memory");
    for (int kt = 0; kt < 8; kt++) {
        const int buf = kt & 1;
        if (kt < 7) {
            load_stage(kt + 1, buf ^ 1);
            asm volatile("cp.async.commit_group;" ::: "memory");
            asm volatile("cp.async.wait_group 1;" ::: "memory");
        } else {
            asm volatile("cp.async.wait_group 0;" ::: "memory");
        }
        __syncthreads();
        uint32_t base = sb + (uint32_t)(buf * SK_STAGE) * 2u;
#pragma unroll
        for (int kk = 0; kk < SK_ROWS; kk += 16) {
            uint32_t a[4][4], b[2][2];
            int krA = kk + (lane & 7) + ((lane >> 4) & 1) * 8;
            int mofA = ((lane >> 3) & 1) * 8;
#pragma unroll
            for (int mi = 0; mi < 4; mi++) {
                int m = wm * 64 + mi * 16 + mofA;
                ldsm_x4_t(a[mi][0], a[mi][1], a[mi][2], a[mi][3],
                          base + (uint32_t)(krA * SK_LD + m) * 2u);
            }
            int krB = kk + (lane & 7) + ((lane >> 3) & 1) * 8;
            int nofB = ((lane >> 4) & 1) * 8;
            {
                int n = 128 + wn * 16 + nofB;
                ldsm_x4_t(b[0][0], b[0][1], b[1][0], b[1][1],
                          base + (uint32_t)(krB * SK_LD + n) * 2u);
            }
#pragma unroll
            for (int mi = 0; mi < 4; mi++)
#pragma unroll
                for (int ni = 0; ni < 2; ni++)
                    mma_bf16(acc[mi][ni], a[mi][0], a[mi][1], a[mi][2], a[mi][3],
                             b[ni][0], b[ni][1]);
        }
        __syncthreads();
    }

#pragma unroll
    for (int mi = 0; mi < 4; mi++)
#pragma unroll
        for (int ni = 0; ni < 2; ni++)
#pragma unroll
            for (int h = 0; h < 2; h++)
#pragma unroll
                for (int w = 0; w < 2; w++) {
                    int gm = ta * 128 + wm * 64 + mi * 16 + (lane >> 2) + 8 * h;
                    int gn = tb * 64 + wn * 16 + ni * 8 + 2 * (lane & 3) + w;
                    atomicAdd(&OUT[gm * DD + gn], acc[mi][ni][2 * h + w]);
                }
}

// ---------------- cvt: Gram fp32 -> mma-fragment bf16 + parallel v-reduction ----------------
// Fragment layout (m16n8k16 B operand): entry (n8, kt, lane) holds
//   .x = bf16x2( C[n][k0], C[n][k0+1] ),  .y = bf16x2( C[n][k0+8], C[n][k0+9] )
// with n = n8*8 + (lane>>2), k0 = kt*16 + (lane&3)*2.   (C symmetric: C[n][k] row-major read)
__global__ void cvt_kernel() {
    const int bid = blockIdx.x, t = threadIdx.x;
    if (bid < 128) {
        int e = bid * 256 + t;            // 0..32767
        const float* SRC = (e >> 14) ? g_Bf : g_Cf;
        uint2* DST = (e >> 14) ? g_Bfrag : g_Cfrag;
        int idx = e & 16383;
        int lane = idx & 31, kt = (idx >> 5) & 15, n8 = idx >> 9;
        int n = n8 * 8 + (lane >> 2);
        int k0 = kt * 16 + (lane & 3) * 2;
        float2 lo = *(const float2*)(SRC + n * 256 + k0);
        float2 hi = *(const float2*)(SRC + n * 256 + k0 + 8);
        __nv_bfloat162 plo = __floats2bfloat162_rn(lo.x, lo.y);
        __nv_bfloat162 phi = __floats2bfloat162_rn(hi.x, hi.y);
        DST[idx] = make_uint2(*(uint32_t*)&plo, *(uint32_t*)&phi);
    } else {
        // blocks 128..159: v1 (32 blocks x 8 cols); 160..191: v2
        const int rb = bid - 128;
        const float* P = (rb < 32) ? g_v1p : g_v2p;
        float* V = (rb < 32) ? g_v1 : g_v2;
        const int base = (rb & 31) * 8;
        const int warp = t >> 5, lane = t & 31;
        const int col = base + warp;
        float s = 0.f;
#pragma unroll
        for (int u = 0; u < 8; u++)
            s += P[(lane * 8 + u) * 256 + col];
#pragma unroll
        for (int o = 16; o; o >>= 1) s += __shfl_xor_sync(~0u, s, o);
        if (lane == 0) V[col] = s;
        if (bid == 191 && t == 0) { g_lsum = 0.f; g_tkf = 0u; }
    }
}

// ---------------- quad: 32-row tiles, B via LDG fragments, 4 CTAs/SM ----------------
// grid: x = 256 row-blocks of 32 rows, y = 2 matrices -> 512 CTAs, one wave at ~3.5/SM
#define QA_LD 264
#define SMA_ELEMS (32 * QA_LD)
#define SMEM_Q (SMA_ELEMS * 2 + (32 + 256 + 256) * 4)

__global__ void __launch_bounds__(256, 4) quad_kernel() {
    extern __shared__ char qs[];
    __nv_bfloat16* smA = (__nv_bfloat16*)qs;
    float* sRow = (float*)(qs + SMA_ELEMS * 2);
    float* sS1  = sRow + 32;
    float* sV   = sS1 + 256;
    uint32_t sa = (uint32_t)__cvta_generic_to_shared(smA);
    const int tid = threadIdx.x, lane = tid & 31, warp = tid >> 5;
    const int wm = warp >> 2, wn = warp & 3;   // wm 0..1 (16 rows), wn 0..3 (32 cols)
    const int rb = blockIdx.x;
    const __nv_bfloat16* A = blockIdx.y ? g_Bb : g_Ab;
    const uint2* Cfr = blockIdx.y ? g_Bfrag : g_Cfrag;
    const float* Vsrc = blockIdx.y ? g_v1 : g_v2;
    float* OUT  = blockIdx.y ? g_S2c : g_S2r;
    float* OUT1 = blockIdx.y ? g_S1c : g_S1r;

    // A tile 32x256 resident (1024 chunks of 16B)
#pragma unroll
    for (int i = 0; i < 4; i++) {
        int c = tid + i * 256;
        int row = c >> 5, col8 = c & 31;
        cp_async16(sa + (uint32_t)(row * QA_LD + col8 * 8) * 2u,
                   A + (size_t)(rb * 32 + row) * DD + col8 * 8);
    }
    asm volatile("cp.async.commit_group;" ::: "memory");
    if (tid < 32) sRow[tid] = 0.f;
    sV[tid] = Vsrc[tid];
    asm volatile("cp.async.wait_group 0;" ::: "memory");
    __syncthreads();

    const int rA = wm * 16 + (lane & 15);
    const int colA = (lane >> 4) << 3;
    float s2[2] = {0.f, 0.f};

    for (int nb = 0; nb < 2; nb++) {
        // b-fragment base for this warp/half: flat index (n8*16 + kt)*32 + lane
        const uint2* bp = Cfr + (size_t)(nb * 16 + wn * 4) * 512 + lane;

        float acc[4][4];
#pragma unroll
        for (int ni = 0; ni < 4; ni++)
#pragma unroll
            for (int q = 0; q < 4; q++) acc[ni][q] = 0.f;

        uint32_t a[2][4];
        uint2 b[2][4];
        auto load_frags = [&](int kt, uint32_t af[4], uint2 bf[4]) {
            ldsm_x4(af[0], af[1], af[2], af[3],
                    sa + (uint32_t)(rA * QA_LD + kt * 16 + colA) * 2u);
#pragma unroll
            for (int ni = 0; ni < 4; ni++)
                bf[ni] = bp[ni * 512 + kt * 32];
        };

        load_frags(0, a[0], b[0]);
#pragma unroll
        for (int kt = 0; kt < 16; kt++) {
            const int cur = kt & 1;
            if (kt < 15) load_frags(kt + 1, a[cur ^ 1], b[cur ^ 1]);
#pragma unroll
            for (int ni = 0; ni < 4; ni++)
                mma_bf16(acc[ni], a[cur][0], a[cur][1], a[cur][2], a[cur][3],
                         b[cur][ni].x, b[cur][ni].y);
        }
        // fold W[r,cl] * x[r,cl] into per-row partials
#pragma unroll
        for (int h = 0; h < 2; h++) {
            int r = wm * 16 + (lane >> 2) + 8 * h;
            float p = 0.f;
#pragma unroll
            for (int ni = 0; ni < 4; ni++)
#pragma unroll
                for (int w = 0; w < 2; w++) {
                    int cl = nb * 128 + wn * 32 + ni * 8 + 2 * (lane & 3) + w;
                    p = fmaf(acc[ni][2 * h + w], __bfloat162float(smA[r * QA_LD + cl]), p);
                }
            s2[h] += p;
        }
    }
#pragma unroll
    for (int h = 0; h < 2; h++) {
        float p = s2[h];
        p += __shfl_xor_sync(~0u, p, 1);
        p += __shfl_xor_sync(~0u, p, 2);
        if ((lane & 3) == 0)
            atomicAdd(&sRow[wm * 16 + (lane >> 2) + 8 * h], p);
    }
    __syncthreads();
    if (tid < 32) OUT[rb * 32 + tid] = sRow[tid];

    // ---- S1: row dot v (thread = (row r in 0..31, eighth q in 0..7)) ----
    {
        int r = tid & 31, q = tid >> 5;
        float s1p = 0.f;
#pragma unroll 8
        for (int k = 0; k < 32; k++) {
            int cl = q * 32 + k;
            s1p = fmaf(__bfloat162float(smA[r * QA_LD + cl]), sV[cl], s1p);
        }
        sS1[q * 32 + r] = s1p;
    }
    __syncthreads();
    if (tid < 32) {
        float s = 0.f;
#pragma unroll
        for (int q = 0; q < 8; q++) s += sS1[q * 32 + tid];
        OUT1[rb * 32 + tid] = s;
    }
}

// ---------------- finalize: scalar per row (R15 exact) ----------------
__device__ __forceinline__ float half_loss(float s1, float s2, float d) {
    float r = sqrtf(fmaxf(s2, 1e-24f));
    float a = 1.0f / r;
    float t = a * d;
    float off = (float)NN + a * s1 + 0.5f - (1.0f + t + 0.5f * t * t);
    float num = t - 0.4f;
    float den = expf(num) + off;
    return num - logf(den);
}

__global__ void finalize_kernel(float* __restrict__ out) {
    const int i = blockIdx.x * 256 + threadIdx.x;   // 32 blocks x 256 = 8192
    float d = g_d[i];
    float l12 = half_loss(g_S1r[i], g_S2r[i], d);
    float l21 = half_loss(g_S1c[i], g_S2c[i], d);
    out[1 + i]      = l12;
    out[1 + NN + i] = l21;
    float v = l12 + l21;
#pragma unroll
    for (int o = 16; o; o >>= 1) v += __shfl_xor_sync(~0u, v, o);
    __shared__ float ws[8];
    if ((threadIdx.x & 31) == 0) ws[threadIdx.x >> 5] = v;
    __syncthreads();
    if (threadIdx.x == 0) {
        float t = 0.f;
#pragma unroll
        for (int k = 0; k < 8; k++) t += ws[k];
        atomicAdd(&g_lsum, t);
        __threadfence();
        unsigned tk = atomicAdd(&g_tkf, 1u);
        if (tk == gridDim.x - 1)
            out[0] = -atomicAdd(&g_lsum, 0.0f) / (float)NN;
    }
}

extern "C" void kernel_launch(void* const* d_in, const int* in_sizes, int n_in,
                              void* d_out, int out_size) {
    const float* x1 = (const float*)d_in[0];
    const float* x2 = (const float*)d_in[1];
    float* out = (float*)d_out;

    cudaFuncSetAttribute(quad_kernel, cudaFuncAttributeMaxDynamicSharedMemorySize, SMEM_Q);

    prep_kernel<<<256, 256>>>(x1, x2);
    syrk_kernel<<<dim3(16, 8, 2), 256>>>();
    cvt_kernel<<<192, 256>>>();
    quad_kernel<<<dim3(256, 2), 256, SMEM_Q>>>();
    finalize_kernel<<<32, 256>>>(out);
}